// round 3
// baseline (speedup 1.0000x reference)
#include <cuda_runtime.h>
#include <stdint.h>

// Problem constants
#define B_ 32
#define C_ 3
#define H_ 512
#define W_ 512
#define G_ 8
#define BINS_ 256
#define CLIPV_ 32
#define NPLANES_ (B_*C_)          // 96
#define NTILES_ (NPLANES_*G_*G_)  // 6144
#define PLANE_PX_ (H_*W_)         // 262144

__device__ unsigned char g_img[NPLANES_ * PLANE_PX_];   // 25 MB quantized image
__device__ unsigned char g_lut[NTILES_ * BINS_];        // 1.5 MB LUTs

// ---------------------------------------------------------------------------
// Kernel 1: per-tile histogram -> clip -> redistribute -> cdf -> LUT
// Dual sub-histograms halve shared-atomic conflicts.
// ---------------------------------------------------------------------------
__global__ __launch_bounds__(256) void hist_lut_kernel(const float* __restrict__ x) {
    const int tile  = blockIdx.x;
    const int plane = tile >> 6;
    const int gy    = (tile >> 3) & 7;
    const int gx    = tile & 7;

    __shared__ int hist[2 * BINS_];
    __shared__ int wsum[8];

    const int t    = threadIdx.x;
    const int lane = t & 31;
    const int warp = t >> 5;
    hist[t] = 0;
    hist[t + 256] = 0;
    __syncthreads();

    int* myhist = hist + ((warp & 4) << 6);   // warps 0-3 -> hist, 4-7 -> hist+256

    const float*   p = x     + (size_t)plane * PLANE_PX_;
    unsigned char* q = g_img + (size_t)plane * PLANE_PX_;

    #pragma unroll
    for (int i = 0; i < 4; i++) {
        int p4 = i * 256 + t;               // 0..1023
        int r  = p4 >> 4;
        int c  = (p4 & 15) << 2;
        size_t off = (size_t)(gy * 64 + r) * W_ + gx * 64 + c;
        float4 v = *reinterpret_cast<const float4*>(p + off);
        int i0 = __float2int_rn(fminf(fmaxf(v.x, 0.0f), 1.0f) * 255.0f);
        int i1 = __float2int_rn(fminf(fmaxf(v.y, 0.0f), 1.0f) * 255.0f);
        int i2 = __float2int_rn(fminf(fmaxf(v.z, 0.0f), 1.0f) * 255.0f);
        int i3 = __float2int_rn(fminf(fmaxf(v.w, 0.0f), 1.0f) * 255.0f);
        uchar4 pk = make_uchar4((unsigned char)i0, (unsigned char)i1,
                                (unsigned char)i2, (unsigned char)i3);
        *reinterpret_cast<uchar4*>(q + off) = pk;
        atomicAdd(&myhist[i0], 1);
        atomicAdd(&myhist[i1], 1);
        atomicAdd(&myhist[i2], 1);
        atomicAdd(&myhist[i3], 1);
    }
    __syncthreads();

    int h = hist[t] + hist[t + 256];
    int clipped = min(h, CLIPV_);
    int ex = h - clipped;
    #pragma unroll
    for (int o = 16; o > 0; o >>= 1) ex += __shfl_down_sync(0xffffffffu, ex, o);
    if (lane == 0) wsum[warp] = ex;
    __syncthreads();
    if (t == 0) {
        int s = 0;
        #pragma unroll
        for (int i = 0; i < 8; i++) s += wsum[i];
        wsum[0] = s;
    }
    __syncthreads();
    const int excess    = wsum[0];
    const int batch_add = excess >> 8;
    const int residual  = excess - (batch_add << 8);
    const int step      = max(BINS_ / max(residual, 1), 1);
    const int add       = ((t % step) == 0 && (t / step) < residual) ? 1 : 0;
    int hf = clipped + batch_add + add;

    // Inclusive scan: warp shfl + cross-warp fixup
    int inc = hf;
    #pragma unroll
    for (int o = 1; o < 32; o <<= 1) {
        int n = __shfl_up_sync(0xffffffffu, inc, o);
        if (lane >= o) inc += n;
    }
    __syncthreads();
    if (lane == 31) wsum[warp] = inc;
    __syncthreads();
    if (t == 0) {
        int s = 0;
        #pragma unroll
        for (int i = 0; i < 8; i++) { int tmp = wsum[i]; wsum[i] = s; s += tmp; }
    }
    __syncthreads();
    float cdf = (float)(inc + wsum[warp]);

    float lut = rintf(cdf * (255.0f / 4096.0f));   // always in [0,255]
    g_lut[(size_t)tile * BINS_ + t] = (unsigned char)lut;
}

// ---------------------------------------------------------------------------
// Kernel 2: bilinear LUT interpolation via pre-decoded float4 lerp tables.
// qlut[quad][v] = (g0, g1-g0, g2, g3-g2). Per pixel: LDS.128 + 3 FMA + rint.
// All arithmetic exact in fp32 -> bit-identical to reference weighted sum.
// ---------------------------------------------------------------------------
__global__ __launch_bounds__(256) void interp_kernel(float* __restrict__ out) {
    const int tile  = blockIdx.x;
    const int plane = tile >> 6;
    const int gy    = (tile >> 3) & 7;
    const int gx    = tile & 7;

    __shared__ float4 qlut[4 * BINS_];   // 16 KB

    const int t = threadIdx.x;
    const unsigned char* lutp = g_lut + (size_t)plane * (G_ * G_ * BINS_);

    const int r_top[2] = { max(gy - 1, 0), gy };
    const int r_bot[2] = { gy, min(gy + 1, G_ - 1) };
    const int c_lft[2] = { max(gx - 1, 0), gx };
    const int c_rgt[2] = { gx, min(gx + 1, G_ - 1) };

    #pragma unroll
    for (int qd = 0; qd < 4; qd++) {
        const int* rr = (qd & 2) ? r_bot : r_top;
        const int* cc = (qd & 1) ? c_rgt : c_lft;
        float b0 = (float)lutp[(rr[0] * G_ + cc[0]) * BINS_ + t];
        float b1 = (float)lutp[(rr[0] * G_ + cc[1]) * BINS_ + t];
        float b2 = (float)lutp[(rr[1] * G_ + cc[0]) * BINS_ + t];
        float b3 = (float)lutp[(rr[1] * G_ + cc[1]) * BINS_ + t];
        qlut[(qd << 8) + t] = make_float4(b0, b1 - b0, b2, b3 - b2);
    }
    __syncthreads();

    const unsigned char* img = g_img + (size_t)plane * PLANE_PX_;
    float* op = out + (size_t)plane * PLANE_PX_;

    const int tr    = t >> 4;           // 0..15
    const int c4    = (t & 15) << 2;    // 0..60
    const int xhalf = (c4 >= 32) ? 1 : 0;

    float wx2[4];
    #pragma unroll
    for (int k = 0; k < 4; k++)
        wx2[k] = (float)((c4 + k + 32) & 63) * (1.0f / 64.0f);

    #pragma unroll
    for (int i = 0; i < 4; i++) {
        const int r = i * 16 + tr;
        const int y = gy * 64 + r;
        const float wy2 = (float)((r + 32) & 63) * (1.0f / 64.0f);
        const float4* ql = &qlut[(((r >= 32) ? 2 : 0) + xhalf) << 8];

        const size_t off = (size_t)y * W_ + gx * 64 + c4;
        uchar4 pix = *reinterpret_cast<const uchar4*>(img + off);
        int vs[4] = { pix.x, pix.y, pix.z, pix.w };

        float res[4];
        #pragma unroll
        for (int k = 0; k < 4; k++) {
            float4 f = ql[vs[k]];
            float top = fmaf(f.y, wx2[k], f.x);
            float bot = fmaf(f.w, wx2[k], f.z);
            float rr  = fmaf(bot - top, wy2, top);
            res[k] = rintf(rr) * (1.0f / 255.0f);
        }
        *reinterpret_cast<float4*>(op + off) = make_float4(res[0], res[1], res[2], res[3]);
    }
}

extern "C" void kernel_launch(void* const* d_in, const int* in_sizes, int n_in,
                              void* d_out, int out_size) {
    const float* x = (const float*)d_in[0];
    float* out = (float*)d_out;

    hist_lut_kernel<<<NTILES_, 256>>>(x);
    interp_kernel<<<NTILES_, 256>>>(out);
}

// round 4
// speedup vs baseline: 1.2500x; 1.2500x over previous
#include <cuda_runtime.h>
#include <stdint.h>

#define B_ 32
#define C_ 3
#define H_ 512
#define W_ 512
#define G_ 8
#define BINS_ 256
#define CLIPV_ 32
#define NPLANES_ (B_*C_)          // 96
#define NTILES_ (NPLANES_*G_*G_)  // 6144
#define PLANE_PX_ (H_*W_)         // 262144

__device__ unsigned char g_img[NPLANES_ * PLANE_PX_];   // 25 MB quantized image
__device__ unsigned char g_lut[NTILES_ * BINS_];        // 1.5 MB LUTs

// ---------------------------------------------------------------------------
// Kernel 1: per-tile histogram -> clip -> redistribute -> cdf -> LUT
// ---------------------------------------------------------------------------
__global__ __launch_bounds__(256) void hist_lut_kernel(const float* __restrict__ x) {
    const int tile  = blockIdx.x;
    const int plane = tile >> 6;
    const int gy    = (tile >> 3) & 7;
    const int gx    = tile & 7;

    __shared__ int hist[2 * BINS_];
    __shared__ int wsum[8];

    const int t    = threadIdx.x;
    const int lane = t & 31;
    const int warp = t >> 5;
    hist[t] = 0;
    hist[t + 256] = 0;
    __syncthreads();

    int* myhist = hist + ((warp & 4) << 6);

    const float*   p = x     + (size_t)plane * PLANE_PX_;
    unsigned char* q = g_img + (size_t)plane * PLANE_PX_;

    #pragma unroll
    for (int i = 0; i < 4; i++) {
        int p4 = i * 256 + t;
        int r  = p4 >> 4;
        int c  = (p4 & 15) << 2;
        size_t off = (size_t)(gy * 64 + r) * W_ + gx * 64 + c;
        float4 v = *reinterpret_cast<const float4*>(p + off);
        int i0 = __float2int_rn(fminf(fmaxf(v.x, 0.0f), 1.0f) * 255.0f);
        int i1 = __float2int_rn(fminf(fmaxf(v.y, 0.0f), 1.0f) * 255.0f);
        int i2 = __float2int_rn(fminf(fmaxf(v.z, 0.0f), 1.0f) * 255.0f);
        int i3 = __float2int_rn(fminf(fmaxf(v.w, 0.0f), 1.0f) * 255.0f);
        uchar4 pk = make_uchar4((unsigned char)i0, (unsigned char)i1,
                                (unsigned char)i2, (unsigned char)i3);
        *reinterpret_cast<uchar4*>(q + off) = pk;
        atomicAdd(&myhist[i0], 1);
        atomicAdd(&myhist[i1], 1);
        atomicAdd(&myhist[i2], 1);
        atomicAdd(&myhist[i3], 1);
    }
    __syncthreads();

    int h = hist[t] + hist[t + 256];
    int clipped = min(h, CLIPV_);
    int ex = h - clipped;
    #pragma unroll
    for (int o = 16; o > 0; o >>= 1) ex += __shfl_down_sync(0xffffffffu, ex, o);
    if (lane == 0) wsum[warp] = ex;
    __syncthreads();
    if (t == 0) {
        int s = 0;
        #pragma unroll
        for (int i = 0; i < 8; i++) s += wsum[i];
        wsum[0] = s;
    }
    __syncthreads();
    const int excess    = wsum[0];
    const int batch_add = excess >> 8;
    const int residual  = excess - (batch_add << 8);
    const int step      = max(BINS_ / max(residual, 1), 1);
    const int add       = ((t % step) == 0 && (t / step) < residual) ? 1 : 0;
    int hf = clipped + batch_add + add;

    int inc = hf;
    #pragma unroll
    for (int o = 1; o < 32; o <<= 1) {
        int n = __shfl_up_sync(0xffffffffu, inc, o);
        if (lane >= o) inc += n;
    }
    __syncthreads();
    if (lane == 31) wsum[warp] = inc;
    __syncthreads();
    if (t == 0) {
        int s = 0;
        #pragma unroll
        for (int i = 0; i < 8; i++) { int tmp = wsum[i]; wsum[i] = s; s += tmp; }
    }
    __syncthreads();
    float cdf = (float)(inc + wsum[warp]);

    float lut = rintf(cdf * (255.0f / 4096.0f));
    g_lut[(size_t)tile * BINS_ + t] = (unsigned char)lut;
}

// ---------------------------------------------------------------------------
// Kernel 2: bilinear LUT interpolation, packed-u32 quadrant LUTs + dp2a.
// qlut[quad][v] = g0 | g1<<8 | g2<<16 | g3<<24 (corners for gray level v).
// Per pixel: 1 LDS.32 + 2 DP2A + I2F + FMUL + FRND + FMUL. Integer-exact:
// result = rint( (sum g_ij * W_ij) / 4096 ) / 255, identical to reference.
// ---------------------------------------------------------------------------
__global__ __launch_bounds__(256) void interp_kernel(float* __restrict__ out) {
    const int tile  = blockIdx.x;
    const int plane = tile >> 6;
    const int gy    = (tile >> 3) & 7;
    const int gx    = tile & 7;

    __shared__ uint32_t qlut[4 * BINS_];

    const int t = threadIdx.x;
    const unsigned char* lutp = g_lut + (size_t)plane * (G_ * G_ * BINS_);

    const int r_top[2] = { max(gy - 1, 0), gy };
    const int r_bot[2] = { gy, min(gy + 1, G_ - 1) };
    const int c_lft[2] = { max(gx - 1, 0), gx };
    const int c_rgt[2] = { gx, min(gx + 1, G_ - 1) };

    #pragma unroll
    for (int qd = 0; qd < 4; qd++) {
        const int* rr = (qd & 2) ? r_bot : r_top;
        const int* cc = (qd & 1) ? c_rgt : c_lft;
        uint32_t b0 = lutp[(rr[0] * G_ + cc[0]) * BINS_ + t];
        uint32_t b1 = lutp[(rr[0] * G_ + cc[1]) * BINS_ + t];
        uint32_t b2 = lutp[(rr[1] * G_ + cc[0]) * BINS_ + t];
        uint32_t b3 = lutp[(rr[1] * G_ + cc[1]) * BINS_ + t];
        qlut[(qd << 8) + t] = b0 | (b1 << 8) | (b2 << 16) | (b3 << 24);
    }
    __syncthreads();

    const unsigned char* img = g_img + (size_t)plane * PLANE_PX_;
    float* op = out + (size_t)plane * PLANE_PX_;

    const int tr    = t >> 4;           // 0..15
    const int c4    = (t & 15) << 2;    // 0..60
    const int xhalf = (c4 >= 32) ? 1 : 0;

    // packedX[k] = (64-WX) | WX<<16, WX = 64*wx2 (integer x-weight)
    uint32_t packedX[4];
    #pragma unroll
    for (int k = 0; k < 4; k++) {
        uint32_t WX = (uint32_t)((c4 + k + 32) & 63);
        packedX[k] = (64u - WX) | (WX << 16);
    }

    #pragma unroll
    for (int i = 0; i < 4; i++) {
        const int r = i * 16 + tr;
        const int y = gy * 64 + r;
        const uint32_t WY = (uint32_t)((r + 32) & 63);
        const uint32_t wyb = WY;          // bottom weight
        const uint32_t wyt = 64u - WY;    // top weight
        const uint32_t* ql = &qlut[(((r >= 32) ? 2 : 0) + xhalf) << 8];

        const size_t off = (size_t)y * W_ + gx * 64 + c4;
        uchar4 pix = *reinterpret_cast<const uchar4*>(img + off);
        int vs[4] = { pix.x, pix.y, pix.z, pix.w };

        float res[4];
        #pragma unroll
        for (int k = 0; k < 4; k++) {
            uint32_t pk   = ql[vs[k]];
            uint32_t Wtop = wyt * packedX[k];   // (64-WY)(64-WX) | (64-WY)WX<<16
            uint32_t Wbot = wyb * packedX[k];   //   WY  (64-WX) |   WY  WX<<16
            uint32_t acc  = __dp2a_lo(Wtop, pk, 0u);     // g0*W00 + g1*W01
            acc           = __dp2a_hi(Wbot, pk, acc);    // + g2*W10 + g3*W11
            float rr = (float)(int)acc;
            res[k] = rintf(rr * (1.0f / 4096.0f)) * (1.0f / 255.0f);
        }
        *reinterpret_cast<float4*>(op + off) = make_float4(res[0], res[1], res[2], res[3]);
    }
}

extern "C" void kernel_launch(void* const* d_in, const int* in_sizes, int n_in,
                              void* d_out, int out_size) {
    const float* x = (const float*)d_in[0];
    float* out = (float*)d_out;

    hist_lut_kernel<<<NTILES_, 256>>>(x);
    interp_kernel<<<NTILES_, 256>>>(out);
}